// round 10
// baseline (speedup 1.0000x reference)
#include <cuda_runtime.h>
#include <cstdint>

#define N_NODES 100000
#define N_EDGES 1600000
#define NFEAT   128
#define NHID    64
#define NCLASS  16

// Scratch (device globals — no allocation allowed in kernel_launch)
__device__ float g_h1[N_NODES * NHID];     // X @ W1 (fp32)
__device__ float g_agg1[N_NODES * NHID];   // scatter1 accumulator
__device__ float g_h2[N_NODES * NCLASS];   // relu(agg1) @ W2

// ---------------- f32x2 packed helpers (SASS FFMA2 — only via PTX) ----------
__device__ __forceinline__ void fma2(unsigned long long& d,
                                     unsigned long long a,
                                     unsigned long long b) {
    asm("fma.rn.f32x2 %0, %1, %2, %3;" : "=l"(d) : "l"(a), "l"(b), "l"(d));
}
__device__ __forceinline__ unsigned long long pack2(float a) {
    unsigned long long r;
    asm("mov.b64 %0, {%1, %1};" : "=l"(r) : "f"(a));
    return r;
}
__device__ __forceinline__ float2 unpack2(unsigned long long p) {
    float2 f;
    asm("mov.b64 {%0, %1}, %2;" : "=f"(f.x), "=f"(f.y) : "l"(p));
    return f;
}
__device__ __forceinline__ uint32_t f2tf32(float f) {
    uint32_t r;
    asm("cvt.rna.tf32.f32 %0, %1;" : "=r"(r) : "f"(f));
    return r;
}

// ---------------------------------------------------------------------------
// Zero d_out only (agg1 zeroing folded into gemm1's epilogue).
// ---------------------------------------------------------------------------
__global__ void zero_kernel(float* __restrict__ out) {
    const int stride = gridDim.x * blockDim.x;
    int i = blockIdx.x * blockDim.x + threadIdx.x;
    const float4 z = make_float4(0.f, 0.f, 0.f, 0.f);
    const int n2 = N_NODES * NCLASS / 4;
    for (int idx = i; idx < n2; idx += stride)
        reinterpret_cast<float4*>(out)[idx] = z;
}

// ---------------------------------------------------------------------------
// GEMM1 (tf32 tensor cores): h1 = X[100000,128] @ W1[128,64], fp32 output.
// Block: 256 threads = 8 warps, tile 128(M) x 64(N), K chunks of 32.
// Epilogue also zeroes this block's agg1 rows (hides the zero pass).
// ---------------------------------------------------------------------------
__global__ __launch_bounds__(256) void gemm1_kernel(const float* __restrict__ X,
                                                    const float* __restrict__ W) {
    __shared__ float Xs[128][36];
    __shared__ float Ws[32][72];

    const int tid  = threadIdx.x;
    const int lane = tid & 31;
    const int warp = tid >> 5;
    const int m0   = blockIdx.x * 128;
    const int wm   = warp >> 1;
    const int wn   = warp & 1;
    const int gr   = lane >> 2;
    const int tg   = lane & 3;

    // zero this block's agg1 rows: 128 rows x 64 floats = 2048 float4
    {
        const float4 z = make_float4(0.f, 0.f, 0.f, 0.f);
#pragma unroll
        for (int t = 0; t < 8; t++) {
            int f4  = tid + t * 256;          // 0..2047
            int row = m0 + (f4 >> 4);
            if (row < N_NODES)
                reinterpret_cast<float4*>(&g_agg1[row * NHID])[f4 & 15] = z;
        }
    }

    float acc[2][4][4];
#pragma unroll
    for (int mi = 0; mi < 2; mi++)
#pragma unroll
        for (int ni = 0; ni < 4; ni++)
#pragma unroll
            for (int r = 0; r < 4; r++) acc[mi][ni][r] = 0.f;

    for (int kc = 0; kc < NFEAT; kc += 32) {
        __syncthreads();
#pragma unroll
        for (int t = 0; t < 4; t++) {
            int f4  = tid + t * 256;
            int row = f4 >> 3;
            int c4  = (f4 & 7) * 4;
            int gm  = m0 + row;
            float4 v = make_float4(0.f, 0.f, 0.f, 0.f);
            if (gm < N_NODES)
                v = *reinterpret_cast<const float4*>(&X[gm * NFEAT + kc + c4]);
            Xs[row][c4 + 0] = __uint_as_float(f2tf32(v.x));
            Xs[row][c4 + 1] = __uint_as_float(f2tf32(v.y));
            Xs[row][c4 + 2] = __uint_as_float(f2tf32(v.z));
            Xs[row][c4 + 3] = __uint_as_float(f2tf32(v.w));
        }
#pragma unroll
        for (int t = 0; t < 2; t++) {
            int f4  = tid + t * 256;
            int row = f4 >> 4;
            int c4  = (f4 & 15) * 4;
            float4 v = *reinterpret_cast<const float4*>(&W[(kc + row) * NHID + c4]);
            Ws[row][c4 + 0] = __uint_as_float(f2tf32(v.x));
            Ws[row][c4 + 1] = __uint_as_float(f2tf32(v.y));
            Ws[row][c4 + 2] = __uint_as_float(f2tf32(v.z));
            Ws[row][c4 + 3] = __uint_as_float(f2tf32(v.w));
        }
        __syncthreads();

#pragma unroll
        for (int ks = 0; ks < 32; ks += 8) {
            uint32_t a[2][4];
#pragma unroll
            for (int mi = 0; mi < 2; mi++) {
                int base = wm * 32 + mi * 16;
                a[mi][0] = __float_as_uint(Xs[base + gr][ks + tg]);
                a[mi][1] = __float_as_uint(Xs[base + gr + 8][ks + tg]);
                a[mi][2] = __float_as_uint(Xs[base + gr][ks + tg + 4]);
                a[mi][3] = __float_as_uint(Xs[base + gr + 8][ks + tg + 4]);
            }
#pragma unroll
            for (int ni = 0; ni < 4; ni++) {
                int cb = wn * 32 + ni * 8;
                uint32_t b0 = __float_as_uint(Ws[ks + tg][cb + gr]);
                uint32_t b1 = __float_as_uint(Ws[ks + tg + 4][cb + gr]);
#pragma unroll
                for (int mi = 0; mi < 2; mi++) {
                    asm volatile(
                        "mma.sync.aligned.m16n8k8.row.col.f32.tf32.tf32.f32 "
                        "{%0,%1,%2,%3}, {%4,%5,%6,%7}, {%8,%9}, {%0,%1,%2,%3};"
                        : "+f"(acc[mi][ni][0]), "+f"(acc[mi][ni][1]),
                          "+f"(acc[mi][ni][2]), "+f"(acc[mi][ni][3])
                        : "r"(a[mi][0]), "r"(a[mi][1]), "r"(a[mi][2]), "r"(a[mi][3]),
                          "r"(b0), "r"(b1));
                }
            }
        }
    }

#pragma unroll
    for (int mi = 0; mi < 2; mi++) {
#pragma unroll
        for (int ni = 0; ni < 4; ni++) {
            int row = m0 + wm * 32 + mi * 16 + gr;
            int col = wn * 32 + ni * 8 + tg * 2;
            if (row < N_NODES)
                *reinterpret_cast<float2*>(&g_h1[row * NHID + col]) =
                    make_float2(acc[mi][ni][0], acc[mi][ni][1]);
            if (row + 8 < N_NODES)
                *reinterpret_cast<float2*>(&g_h1[(row + 8) * NHID + col]) =
                    make_float2(acc[mi][ni][2], acc[mi][ni][3]);
        }
    }
}

// ---------------------------------------------------------------------------
// scatter1: agg1[dst] += w * h1[src].  16 threads/edge, one float4 gather +
// one red.global.add.v4.f32 per thread (measured-best layout).
// ---------------------------------------------------------------------------
__global__ __launch_bounds__(256) void scatter1_kernel(const int* __restrict__ ei,
                                                       const float* __restrict__ ew) {
    int gid = blockIdx.x * blockDim.x + threadIdx.x;
    int e = gid >> 4;
    int c = gid & 15;
    if (e >= N_EDGES) return;
    int s = ei[e];
    int d = ei[N_EDGES + e];
    float w = ew[e];
    float4 v = *reinterpret_cast<const float4*>(&g_h1[s * NHID + c * 4]);
    float* dst = &g_agg1[d * NHID + c * 4];
    asm volatile("red.global.add.v4.f32 [%0], {%1, %2, %3, %4};"
                 :: "l"(dst), "f"(v.x * w), "f"(v.y * w), "f"(v.z * w), "f"(v.w * w)
                 : "memory");
}

// ---------------------------------------------------------------------------
// GEMM2 (+fused ReLU): h2 = relu(agg1)[100000,64] @ W2[64,16], fp32 output.
// Column-split, 2 threads per node: each reads the full 64-k row (pair
// threads broadcast-share the row in L1) and computes 8 of the 16 outputs
// (4 f32x2 accumulators). 200K threads -> double the latency-hiding of the
// 1-thread/node version, no shfl, no redundant DRAM.
// ---------------------------------------------------------------------------
__global__ __launch_bounds__(256) void gemm2_kernel(const float* __restrict__ W2) {
    __shared__ float Ws[NHID * NCLASS];  // [64][16] row-major, 1024 floats
    const int tid = threadIdx.x;
    reinterpret_cast<float4*>(Ws)[tid] = reinterpret_cast<const float4*>(W2)[tid];
    __syncthreads();

    int gid  = blockIdx.x * blockDim.x + tid;
    int node = gid >> 1;
    int half = gid & 1;                  // output cols [half*8, half*8+8)
    if (node >= N_NODES) return;

    unsigned long long acc[4] = {};      // 8 output cols as 4 f32x2 pairs

#pragma unroll
    for (int k4 = 0; k4 < NHID / 4; k4++) {
        float4 a = *reinterpret_cast<const float4*>(&g_agg1[node * NHID + k4 * 4]);
        a.x = fmaxf(a.x, 0.f); a.y = fmaxf(a.y, 0.f);
        a.z = fmaxf(a.z, 0.f); a.w = fmaxf(a.w, 0.f);
#pragma unroll
        for (int j = 0; j < 4; j++) {
            float av = (j == 0) ? a.x : (j == 1) ? a.y : (j == 2) ? a.z : a.w;
            unsigned long long ap = pack2(av);
            const ulonglong2* wr = reinterpret_cast<const ulonglong2*>(
                &Ws[(k4 * 4 + j) * NCLASS + half * 8]);
            ulonglong2 wa = wr[0];
            ulonglong2 wb = wr[1];
            fma2(acc[0], ap, wa.x); fma2(acc[1], ap, wa.y);
            fma2(acc[2], ap, wb.x); fma2(acc[3], ap, wb.y);
        }
    }

#pragma unroll
    for (int p = 0; p < 2; p++) {
        float2 lo = unpack2(acc[p * 2 + 0]);
        float2 hi = unpack2(acc[p * 2 + 1]);
        *reinterpret_cast<float4*>(&g_h2[node * NCLASS + half * 8 + p * 4]) =
            make_float4(lo.x, lo.y, hi.x, hi.y);
    }
}

// ---------------------------------------------------------------------------
// scatter2: out[dst] += w * h2[src].  4 threads/edge, float4 gather + red.v4.
// ---------------------------------------------------------------------------
__global__ __launch_bounds__(256) void scatter2_kernel(const int* __restrict__ ei,
                                                       const float* __restrict__ ew,
                                                       float* __restrict__ out) {
    int gid = blockIdx.x * blockDim.x + threadIdx.x;
    int e = gid >> 2;
    int c = gid & 3;
    if (e >= N_EDGES) return;
    int s = ei[e];
    int d = ei[N_EDGES + e];
    float w = ew[e];
    float4 v = *reinterpret_cast<const float4*>(&g_h2[s * NCLASS + c * 4]);
    float* dst = &out[d * NCLASS + c * 4];
    asm volatile("red.global.add.v4.f32 [%0], {%1, %2, %3, %4};"
                 :: "l"(dst), "f"(v.x * w), "f"(v.y * w), "f"(v.z * w), "f"(v.w * w)
                 : "memory");
}

// ---------------------------------------------------------------------------
extern "C" void kernel_launch(void* const* d_in, const int* in_sizes, int n_in,
                              void* d_out, int out_size) {
    const float* x   = (const float*)d_in[0];
    const int*   ei1 = (const int*)  d_in[1];
    const int*   ei2 = (const int*)  d_in[2];
    const float* ew1 = (const float*)d_in[3];
    const float* ew2 = (const float*)d_in[4];
    const float* W1  = (const float*)d_in[5];
    const float* W2  = (const float*)d_in[6];
    float* out = (float*)d_out;

    zero_kernel<<<512, 256>>>(out);
    gemm1_kernel<<<(N_NODES + 127) / 128, 256>>>(x, W1);
    scatter1_kernel<<<(N_EDGES * 16 + 255) / 256, 256>>>(ei1, ew1);
    gemm2_kernel<<<(N_NODES * 2 + 255) / 256, 256>>>(W2);
    scatter2_kernel<<<(N_EDGES * 4 + 255) / 256, 256>>>(ei2, ew2, out);
}